// round 6
// baseline (speedup 1.0000x reference)
#include <cuda_runtime.h>
#include <cuda_fp16.h>
#include <cstdint>

// ---------------------------------------------------------------------------
// SelfEquiConv as two fused outer-product GEMMs (fp16 HMMA, fp32 accum)
//   GEMM1: X1(128x5120) @ W1(5120x96) -> [z_s | z_g]
//   GEMM2: X2(384x4096) @ W2(4096x32) -> z_v
// R5: barrier-free mainloops. B streamed per-warp via LDG (L1/L2-hot) with
//     1-kt register double buffer. No smem B, no cp.async, no mainloop syncs.
// ---------------------------------------------------------------------------

#define TILE_E   128
#define NTHR     512

#define W1_U32  (320*12*32*2)
#define W2_U32  (256*4*32*2)

__device__ __align__(16) uint32_t g_W1[W1_U32];
__device__ __align__(16) uint32_t g_W2[W2_U32];

// ------------------------- smem layout (bytes) -----------------------------
#define OFF_S1   0        // 128 x 66 half   = 16896
#define OFF_S2   16896    // 128 x 72 half   = 18432
#define OFF_V1   35328    // 3 x 128 x 34 h  = 26112
#define OFF_V2   61440    // 3 x 128 x 40 h  = 30720
#define OFF_ZSG  92160    // 128 x 98 float  = 50176
#define SMEM_BYTES 142336
// aliases: zv (384x34 f32 = 52224) at OFF_S1 (post-GEMM2),
//          wls (16384) + wlv (4096) at OFF_V2 (post fragment-hoist)

#define P_S1 66
#define P_S2 72
#define P_V1 34
#define P_V2 40

// --------------------------- device helpers --------------------------------
__device__ __forceinline__ void ldm4(uint32_t r[4], const __half* p) {
    uint32_t a = (uint32_t)__cvta_generic_to_shared(p);
    asm volatile("ldmatrix.sync.aligned.m8n8.x4.shared.b16 {%0,%1,%2,%3}, [%4];"
                 : "=r"(r[0]), "=r"(r[1]), "=r"(r[2]), "=r"(r[3]) : "r"(a));
}

__device__ __forceinline__ void mma_f16(float c[4], const uint32_t a[4],
                                        uint32_t b0, uint32_t b1) {
    asm volatile("mma.sync.aligned.m16n8k16.row.col.f32.f16.f16.f32 "
                 "{%0,%1,%2,%3}, {%4,%5,%6,%7}, {%8,%9}, {%0,%1,%2,%3};"
                 : "+f"(c[0]), "+f"(c[1]), "+f"(c[2]), "+f"(c[3])
                 : "r"(a[0]), "r"(a[1]), "r"(a[2]), "r"(a[3]),
                   "r"(b0), "r"(b1));
}

__device__ __forceinline__ uint32_t h2u(__half h) {
    __half2 t = __half2half2(h);
    return *reinterpret_cast<uint32_t*>(&t);
}
__device__ __forceinline__ uint32_t hmul2u(uint32_t x, uint32_t s) {
    __half2 a = *reinterpret_cast<__half2*>(&x);
    __half2 b = *reinterpret_cast<__half2*>(&s);
    __half2 c = __hmul2(a, b);
    return *reinterpret_cast<uint32_t*>(&c);
}
__device__ __forceinline__ uint32_t hfma2u(uint32_t x, uint32_t s, uint32_t acc) {
    __half2 a = *reinterpret_cast<__half2*>(&x);
    __half2 b = *reinterpret_cast<__half2*>(&s);
    __half2 c = *reinterpret_cast<__half2*>(&acc);
    __half2 d = __hfma2(a, b, c);
    return *reinterpret_cast<uint32_t*>(&d);
}

#define LOADB12(dst, p) do { \
    dst[0]=(p)[0];   dst[1]=(p)[1];   dst[2]=(p)[64];  dst[3]=(p)[65];  \
    dst[4]=(p)[128]; dst[5]=(p)[129]; dst[6]=(p)[192]; dst[7]=(p)[193]; \
    dst[8]=(p)[256]; dst[9]=(p)[257]; dst[10]=(p)[320]; dst[11]=(p)[321]; } while(0)

#define LOADB4(dst, p) do { \
    dst[0]=(p)[0]; dst[1]=(p)[1]; dst[2]=(p)[64]; dst[3]=(p)[65]; } while(0)

// ---------------------------------------------------------------------------
// Weight prep (unchanged): fold A_* scales, fp32->fp16, B-frag order.
// g_W[((kt*NT+nt)*32+lane)*2 + r] = half2{ W[k0,n], W[k0+1,n] },
// k0 = kt*16 + (lane&3)*2 + r*8, n = nt*8 + lane/4.
// ---------------------------------------------------------------------------
__global__ void prep_kernel(const float* __restrict__ wss_s, const float* __restrict__ wvv_s,
                            const float* __restrict__ wss_g, const float* __restrict__ wvv_g,
                            const float* __restrict__ wsv_v, const float* __restrict__ wvs_v) {
    int t = blockIdx.x * blockDim.x + threadIdx.x;
    const float A_SS = rsqrtf(8192.0f);
    const float A_VV = rsqrtf(6144.0f);
    const float A_SV = rsqrtf(12288.0f);

    if (t < 320 * 12 * 32) {
        int lane = t & 31;
        int n = ((t >> 5) % 12) * 8 + (lane >> 2);
        int kt = t / (12 * 32);
#pragma unroll
        for (int r = 0; r < 2; ++r) {
            float f[2];
#pragma unroll
            for (int q = 0; q < 2; ++q) {
                int k = kt * 16 + (lane & 3) * 2 + r * 8 + q;
                float val;
                if (k < 4096) {
                    int u = k >> 6, v = k & 63;
                    val = (n < 64) ? A_SS * wss_s[(u * 64 + v) * 64 + n]
                                   : A_SS * wss_g[(u * 64 + v) * 32 + (n - 64)];
                } else {
                    int kk = k - 4096;
                    int u = kk >> 5, v = kk & 31;
                    val = (n < 64) ? A_VV * wvv_s[(u * 32 + v) * 64 + n]
                                   : A_VV * wvv_g[(u * 32 + v) * 32 + (n - 64)];
                }
                f[q] = val;
            }
            __half2 h = __floats2half2_rn(f[0], f[1]);
            g_W1[t * 2 + r] = *reinterpret_cast<uint32_t*>(&h);
        }
    } else if (t < 320 * 12 * 32 + 256 * 4 * 32) {
        int t2 = t - 320 * 12 * 32;
        int lane = t2 & 31;
        int n = ((t2 >> 5) & 3) * 8 + (lane >> 2);
        int kt = t2 >> 7;
#pragma unroll
        for (int r = 0; r < 2; ++r) {
            float f[2];
#pragma unroll
            for (int q = 0; q < 2; ++q) {
                int k = kt * 16 + (lane & 3) * 2 + r * 8 + q;
                float val;
                if (k < 2048) {
                    int u = k >> 5, v = k & 31;
                    val = A_SV * wsv_v[(u * 32 + v) * 32 + n];
                } else {
                    int kk = k - 2048;
                    int u = kk >> 6, v = kk & 63;
                    val = A_SV * wvs_v[(u * 64 + v) * 32 + n];
                }
                f[q] = val;
            }
            __half2 h = __floats2half2_rn(f[0], f[1]);
            g_W2[t2 * 2 + r] = *reinterpret_cast<uint32_t*>(&h);
        }
    }
}

// ---------------------------------------------------------------------------
// Main fused kernel: 512 threads (16 warps), wm=warp&7 -> M-tile, wn=warp>>3
// -> N-half. Mainloops are barrier-free.
// ---------------------------------------------------------------------------
__global__ void __launch_bounds__(NTHR, 1)
main_kernel(const float* __restrict__ f1, const float* __restrict__ f2,
            const float* __restrict__ wl_s_g, const float* __restrict__ wl_v_g,
            float* __restrict__ out, int E) {
    extern __shared__ char sm[];
    __half* s1h = (__half*)(sm + OFF_S1);
    __half* s2h = (__half*)(sm + OFF_S2);
    __half* v1h = (__half*)(sm + OFF_V1);
    __half* v2h = (__half*)(sm + OFF_V2);
    float*  zsg = (float*)(sm + OFF_ZSG);
    float*  zv  = (float*)(sm + OFF_S1);
    float*  wls = (float*)(sm + OFF_V2);
    float*  wlv = (float*)(sm + OFF_V2 + 16384);

    const int tid  = threadIdx.x;
    const int warp = tid >> 5;
    const int lane = tid & 31;
    const int wm   = warp & 7;
    const int wn   = warp >> 3;
    const int e0   = blockIdx.x * TILE_E;

    // ---- stage inputs as fp16 (zero-padded past E) ----
    for (int idx = tid; idx < TILE_E * 160; idx += NTHR) {
        int e = idx / 160;
        int c = idx - e * 160;
        float a = 0.f, b = 0.f;
        if (e0 + e < E) {
            a = f1[(size_t)(e0 + e) * 160 + c];
            b = f2[(size_t)(e0 + e) * 160 + c];
        }
        if (c < 64) {
            s1h[e * P_S1 + c] = __float2half_rn(a);
            s2h[e * P_S2 + c] = __float2half_rn(b);
        } else {
            int cc = c - 64;
            int u = cc / 3, i = cc - u * 3;
            v1h[(i * 128 + e) * P_V1 + u] = __float2half_rn(a);
            v2h[(i * 128 + e) * P_V2 + u] = __float2half_rn(b);
        }
    }
    __syncthreads();

    const int r0 = wm * 16 + (lane >> 2);
    const __half* lm_s2 = s2h + (wm * 16 + (lane & 15)) * P_S2 + ((lane >> 4) << 3);
    const __half* lm_v2 = v2h + (wm * 16 + (lane & 15)) * P_V2 + ((lane >> 4) << 3);

    // ---- hoist ALL A-side fragments (reused across the entire K dim) ----
    uint32_t fs2[4][4];
    uint32_t fv2[3][2][4];
#pragma unroll
    for (int j = 0; j < 4; ++j) ldm4(fs2[j], lm_s2 + j * 16);
#pragma unroll
    for (int i = 0; i < 3; ++i)
#pragma unroll
        for (int j = 0; j < 2; ++j)
            ldm4(fv2[i][j], lm_v2 + i * (128 * P_V2) + j * 16);
    __syncthreads();   // v2h dead after this; epilogue weights overwrite it

    // ---- load epilogue weights into smem (overlaps GEMM1) ----
    for (int idx = tid; idx < 4096; idx += NTHR) wls[idx] = wl_s_g[idx];
    for (int idx = tid; idx < 1024; idx += NTHR) wlv[idx] = wl_v_g[idx];

    // =========================== GEMM1 (barrier-free) ===========================
    const uint32_t* gB1 = g_W1 + wn * 384 + lane * 2;
    float acc1[6][4];
#pragma unroll
    for (int nt = 0; nt < 6; ++nt)
        acc1[nt][0] = acc1[nt][1] = acc1[nt][2] = acc1[nt][3] = 0.f;

    uint32_t Bb[12];
    LOADB12(Bb, gB1);

    for (int c = 0; c < 80; ++c) {
        if (c < 64) {                       // ss: X = s1[e,u=c] * s2[e,v]
            uint32_t ha = h2u(s1h[r0 * P_S1 + c]);
            uint32_t hb = h2u(s1h[(r0 + 8) * P_S1 + c]);
#pragma unroll
            for (int kl = 0; kl < 4; ++kl) {
                int kt = c * 4 + kl;
                int ktn = (kt + 1 < 320) ? kt + 1 : kt;
                const uint32_t* p = gB1 + ktn * 768;
                uint32_t Bn[12];
                LOADB12(Bn, p);
                uint32_t a[4];
                a[0] = hmul2u(fs2[kl][0], ha); a[1] = hmul2u(fs2[kl][1], hb);
                a[2] = hmul2u(fs2[kl][2], ha); a[3] = hmul2u(fs2[kl][3], hb);
#pragma unroll
                for (int nt = 0; nt < 6; ++nt)
                    mma_f16(acc1[nt], a, Bb[2 * nt], Bb[2 * nt + 1]);
#pragma unroll
                for (int j = 0; j < 12; ++j) Bb[j] = Bn[j];
            }
        } else {                            // vv: X = sum_i v1[e,u,i]*v2[e,v,i]
            int c2 = c - 64;
#pragma unroll
            for (int h = 0; h < 2; ++h) {
                int u = 2 * c2 + h;
                uint32_t ha[3], hb[3];
#pragma unroll
                for (int i = 0; i < 3; ++i) {
                    ha[i] = h2u(v1h[(i * 128 + r0) * P_V1 + u]);
                    hb[i] = h2u(v1h[(i * 128 + r0 + 8) * P_V1 + u]);
                }
#pragma unroll
                for (int vb = 0; vb < 2; ++vb) {
                    int kt = c * 4 + h * 2 + vb;
                    int ktn = (kt + 1 < 320) ? kt + 1 : kt;
                    const uint32_t* p = gB1 + ktn * 768;
                    uint32_t Bn[12];
                    LOADB12(Bn, p);
                    uint32_t a[4];
                    a[0] = hmul2u(fv2[0][vb][0], ha[0]);
                    a[1] = hmul2u(fv2[0][vb][1], hb[0]);
                    a[2] = hmul2u(fv2[0][vb][2], ha[0]);
                    a[3] = hmul2u(fv2[0][vb][3], hb[0]);
#pragma unroll
                    for (int i = 1; i < 3; ++i) {
                        a[0] = hfma2u(fv2[i][vb][0], ha[i], a[0]);
                        a[1] = hfma2u(fv2[i][vb][1], hb[i], a[1]);
                        a[2] = hfma2u(fv2[i][vb][2], ha[i], a[2]);
                        a[3] = hfma2u(fv2[i][vb][3], hb[i], a[3]);
                    }
#pragma unroll
                    for (int nt = 0; nt < 6; ++nt)
                        mma_f16(acc1[nt], a, Bb[2 * nt], Bb[2 * nt + 1]);
#pragma unroll
                    for (int j = 0; j < 12; ++j) Bb[j] = Bn[j];
                }
            }
        }
    }

    // ---- write back z_sg (fresh region; no barrier needed) ----
    {
        int row = wm * 16 + (lane >> 2);
        int colb = (lane & 3) * 2;
#pragma unroll
        for (int nt = 0; nt < 6; ++nt) {
            int col = (wn * 6 + nt) * 8 + colb;
            *(float2*)&zsg[row * 98 + col]       = make_float2(acc1[nt][0], acc1[nt][1]);
            *(float2*)&zsg[(row + 8) * 98 + col] = make_float2(acc1[nt][2], acc1[nt][3]);
        }
    }

    // =========================== GEMM2 (barrier-free) ===========================
    const uint32_t* gB2 = g_W2 + wn * 128 + lane * 2;
    float acc2[3][2][4];
#pragma unroll
    for (int i = 0; i < 3; ++i)
#pragma unroll
        for (int nt = 0; nt < 2; ++nt)
            acc2[i][nt][0] = acc2[i][nt][1] = acc2[i][nt][2] = acc2[i][nt][3] = 0.f;

    uint32_t Cb[4];
    LOADB4(Cb, gB2);

    for (int c = 0; c < 32; ++c) {
        if (c < 16) {                       // X = s1[e,u] * v2[e,v,i]
#pragma unroll
            for (int uu = 0; uu < 4; ++uu) {
                int u = 4 * c + uu;
                uint32_t ha = h2u(s1h[r0 * P_S1 + u]);
                uint32_t hb = h2u(s1h[(r0 + 8) * P_S1 + u]);
#pragma unroll
                for (int vb = 0; vb < 2; ++vb) {
                    int kt = c * 8 + uu * 2 + vb;
                    int ktn = (kt + 1 < 256) ? kt + 1 : kt;
                    const uint32_t* p = gB2 + ktn * 256;
                    uint32_t Cn[4];
                    LOADB4(Cn, p);
                    uint32_t ai[3][4];
#pragma unroll
                    for (int i = 0; i < 3; ++i) {
                        ai[i][0] = hmul2u(fv2[i][vb][0], ha);
                        ai[i][1] = hmul2u(fv2[i][vb][1], hb);
                        ai[i][2] = hmul2u(fv2[i][vb][2], ha);
                        ai[i][3] = hmul2u(fv2[i][vb][3], hb);
                    }
#pragma unroll
                    for (int nt = 0; nt < 2; ++nt) {
#pragma unroll
                        for (int i = 0; i < 3; ++i)
                            mma_f16(acc2[i][nt], ai[i], Cb[2 * nt], Cb[2 * nt + 1]);
                    }
#pragma unroll
                    for (int j = 0; j < 4; ++j) Cb[j] = Cn[j];
                }
            }
        } else {                            // X = v1[e,u,i] * s2[e,v]
            int c2 = c - 16;
#pragma unroll
            for (int h = 0; h < 2; ++h) {
                int u = 2 * c2 + h;
                uint32_t ha[3], hb[3];
#pragma unroll
                for (int i = 0; i < 3; ++i) {
                    ha[i] = h2u(v1h[(i * 128 + r0) * P_V1 + u]);
                    hb[i] = h2u(v1h[(i * 128 + r0 + 8) * P_V1 + u]);
                }
#pragma unroll
                for (int vb = 0; vb < 4; ++vb) {
                    int kt = c * 8 + h * 4 + vb;
                    int ktn = (kt + 1 < 256) ? kt + 1 : kt;
                    const uint32_t* p = gB2 + ktn * 256;
                    uint32_t Cn[4];
                    LOADB4(Cn, p);
                    uint32_t ai[3][4];
#pragma unroll
                    for (int i = 0; i < 3; ++i) {
                        ai[i][0] = hmul2u(fs2[vb][0], ha[i]);
                        ai[i][1] = hmul2u(fs2[vb][1], hb[i]);
                        ai[i][2] = hmul2u(fs2[vb][2], ha[i]);
                        ai[i][3] = hmul2u(fs2[vb][3], hb[i]);
                    }
#pragma unroll
                    for (int nt = 0; nt < 2; ++nt) {
#pragma unroll
                        for (int i = 0; i < 3; ++i)
                            mma_f16(acc2[i][nt], ai[i], Cb[2 * nt], Cb[2 * nt + 1]);
                    }
#pragma unroll
                    for (int j = 0; j < 4; ++j) Cb[j] = Cn[j];
                }
            }
        }
    }

    __syncthreads();   // all GEMM2 smem reads done; zsg complete

    // ---- write back z_v (aliases input region; inputs dead) ----
    {
        int rr = wm * 16 + (lane >> 2);
        int colb = (lane & 3) * 2;
#pragma unroll
        for (int i = 0; i < 3; ++i)
#pragma unroll
            for (int nt = 0; nt < 2; ++nt) {
                int row = i * 128 + rr;
                int col = (wn * 2 + nt) * 8 + colb;
                *(float2*)&zv[row * 34 + col]       = make_float2(acc2[i][nt][0], acc2[i][nt][1]);
                *(float2*)&zv[(row + 8) * 34 + col] = make_float2(acc2[i][nt][2], acc2[i][nt][3]);
            }
    }

    // ---- activations on z_sg ----
    for (int idx = tid; idx < 128 * 96; idx += NTHR) {
        int e = idx / 96;
        int cc = idx - e * 96;
        float v = zsg[e * 98 + cc];
        float sg = 1.f / (1.f + __expf(-v));
        zsg[e * 98 + cc] = (cc < 64) ? v * sg : sg;
    }
    __syncthreads();

    // ---- gate z_v by sigmoid(z_g) ----
    for (int idx = tid; idx < 384 * 32; idx += NTHR) {
        int row = idx >> 5, v = idx & 31;
        int e = row & 127;
        zv[row * 34 + v] *= zsg[e * 98 + 64 + v];
    }
    __syncthreads();

    // ---- s_out: silu(z_s) @ wl_s * 1/8 ----
    {
        int e = tid >> 2;
        int wbase = (tid & 3) * 16;
        bool valid = (e0 + e) < E;
#pragma unroll
        for (int wb = 0; wb < 16; wb += 8) {
            float accs[8];
#pragma unroll
            for (int j = 0; j < 8; ++j) accs[j] = 0.f;
            for (int u = 0; u < 64; ++u) {
                float zs = zsg[e * 98 + u];
                float4 w0 = *(const float4*)&wls[u * 64 + wbase + wb];
                float4 w1 = *(const float4*)&wls[u * 64 + wbase + wb + 4];
                accs[0] += zs * w0.x; accs[1] += zs * w0.y;
                accs[2] += zs * w0.z; accs[3] += zs * w0.w;
                accs[4] += zs * w1.x; accs[5] += zs * w1.y;
                accs[6] += zs * w1.z; accs[7] += zs * w1.w;
            }
            if (valid) {
                float4 o0 = make_float4(accs[0] * 0.125f, accs[1] * 0.125f,
                                        accs[2] * 0.125f, accs[3] * 0.125f);
                float4 o1 = make_float4(accs[4] * 0.125f, accs[5] * 0.125f,
                                        accs[6] * 0.125f, accs[7] * 0.125f);
                *(float4*)&out[(size_t)(e0 + e) * 160 + wbase + wb]     = o0;
                *(float4*)&out[(size_t)(e0 + e) * 160 + wbase + wb + 4] = o1;
            }
        }
    }

    // ---- v_out: (g * z_v) @ wl_v * 1/sqrt(32) ----
    const float R32 = 0.17677669529663687f;
    for (int r = tid; r < 384; r += NTHR) {
        int i = r >> 7;
        int e = r & 127;
        float acc[32];
#pragma unroll
        for (int w = 0; w < 32; ++w) acc[w] = 0.f;
        for (int v = 0; v < 32; ++v) {
            float zval = zv[r * 34 + v];
#pragma unroll
            for (int w4 = 0; w4 < 32; w4 += 4) {
                float4 wv = *(const float4*)&wlv[v * 32 + w4];
                acc[w4]     += zval * wv.x;
                acc[w4 + 1] += zval * wv.y;
                acc[w4 + 2] += zval * wv.z;
                acc[w4 + 3] += zval * wv.w;
            }
        }
        if (e0 + e < E) {
#pragma unroll
            for (int w = 0; w < 32; ++w)
                out[(size_t)(e0 + e) * 160 + 64 + w * 3 + i] = acc[w] * R32;
        }
    }
}

// ---------------------------------------------------------------------------
extern "C" void kernel_launch(void* const* d_in, const int* in_sizes, int n_in,
                              void* d_out, int out_size) {
    const float* f1    = (const float*)d_in[0];
    const float* f2    = (const float*)d_in[1];
    const float* wss_s = (const float*)d_in[4];
    const float* wvv_s = (const float*)d_in[5];
    const float* wss_g = (const float*)d_in[6];
    const float* wvv_g = (const float*)d_in[7];
    const float* wsv_v = (const float*)d_in[8];
    const float* wvs_v = (const float*)d_in[9];
    const float* wl_s  = (const float*)d_in[10];
    const float* wl_v  = (const float*)d_in[11];
    float* out = (float*)d_out;

    int E = in_sizes[0] / 160;

    prep_kernel<<<608, 256>>>(wss_s, wvv_s, wss_g, wvv_g, wsv_v, wvs_v);

    cudaFuncSetAttribute(main_kernel, cudaFuncAttributeMaxDynamicSharedMemorySize,
                         SMEM_BYTES);
    int ntiles = (E + TILE_E - 1) / TILE_E;
    main_kernel<<<ntiles, NTHR, SMEM_BYTES>>>(f1, f2, wl_s, wl_v, out, E);
}

// round 8
// speedup vs baseline: 1.0433x; 1.0433x over previous
#include <cuda_runtime.h>
#include <cuda_fp16.h>
#include <cstdint>

// ---------------------------------------------------------------------------
// SelfEquiConv as two fused outer-product GEMMs (fp16 HMMA, fp32 accum)
//   GEMM1: X1(128x5120) @ W1(5120x96) -> [z_s | z_g]
//   GEMM2: X2(384x4096) @ W2(4096x32) -> z_v
// R8: weights repacked so each lane's B fragment is contiguous ->
//     3x LDG.128 (GEMM1) / 1x LDG.128 (GEMM2) per kt, full line density.
//     Depth-2 register prefetch to cover L2-class latency. No tcgen05
//     (harness ptxas targets bare sm_103; tcgen05 requires sm_103a).
// ---------------------------------------------------------------------------

#define TILE_E   128
#define NTHR     512

#define W1_U32  (320*2*3*128)   // 245760
#define W2_U32  (256*2*128)     // 65536

__device__ __align__(16) uint32_t g_W1[W1_U32];
__device__ __align__(16) uint32_t g_W2[W2_U32];

// ------------------------- smem layout (bytes) -----------------------------
#define OFF_S1   0        // 128 x 66 half   = 16896
#define OFF_S2   16896    // 128 x 72 half   = 18432
#define OFF_V1   35328    // 3 x 128 x 34 h  = 26112
#define OFF_V2   61440    // 3 x 128 x 40 h  = 30720
#define OFF_ZSG  92160    // 128 x 98 float  = 50176
#define SMEM_BYTES 142336
// aliases: zv (384x34 f32) at OFF_S1 (post-GEMM2), wls+wlv at OFF_V2

#define P_S1 66
#define P_S2 72
#define P_V1 34
#define P_V2 40

// --------------------------- device helpers --------------------------------
__device__ __forceinline__ void ldm4(uint32_t r[4], const __half* p) {
    uint32_t a = (uint32_t)__cvta_generic_to_shared(p);
    asm volatile("ldmatrix.sync.aligned.m8n8.x4.shared.b16 {%0,%1,%2,%3}, [%4];"
                 : "=r"(r[0]), "=r"(r[1]), "=r"(r[2]), "=r"(r[3]) : "r"(a));
}

__device__ __forceinline__ void mma_f16(float c[4], const uint32_t a[4],
                                        uint32_t b0, uint32_t b1) {
    asm volatile("mma.sync.aligned.m16n8k16.row.col.f32.f16.f16.f32 "
                 "{%0,%1,%2,%3}, {%4,%5,%6,%7}, {%8,%9}, {%0,%1,%2,%3};"
                 : "+f"(c[0]), "+f"(c[1]), "+f"(c[2]), "+f"(c[3])
                 : "r"(a[0]), "r"(a[1]), "r"(a[2]), "r"(a[3]),
                   "r"(b0), "r"(b1));
}

__device__ __forceinline__ uint32_t h2u(__half h) {
    __half2 t = __half2half2(h); return *reinterpret_cast<uint32_t*>(&t);
}
__device__ __forceinline__ uint32_t hmul2u(uint32_t x, uint32_t s) {
    __half2 c = __hmul2(*(__half2*)&x, *(__half2*)&s); return *(uint32_t*)&c;
}
__device__ __forceinline__ uint32_t hfma2u(uint32_t x, uint32_t s, uint32_t a) {
    __half2 c = __hfma2(*(__half2*)&x, *(__half2*)&s, *(__half2*)&a); return *(uint32_t*)&c;
}

// load 12 contiguous-per-lane uint32 as 3x LDG.128
__device__ __forceinline__ void loadB12(uint32_t d[12], const uint4* p) {
    uint4 x0 = __ldg(p);
    uint4 x1 = __ldg(p + 32);
    uint4 x2 = __ldg(p + 64);
    d[0]=x0.x; d[1]=x0.y; d[2]=x0.z;  d[3]=x0.w;
    d[4]=x1.x; d[5]=x1.y; d[6]=x1.z;  d[7]=x1.w;
    d[8]=x2.x; d[9]=x2.y; d[10]=x2.z; d[11]=x2.w;
}
__device__ __forceinline__ void loadB4(uint32_t d[4], const uint4* p) {
    uint4 x0 = __ldg(p);
    d[0]=x0.x; d[1]=x0.y; d[2]=x0.z; d[3]=x0.w;
}

// ---------------------------------------------------------------------------
// Weight prep: fold A_* scales, fp32->fp16, pack so each (kt, wn, lane) owns
// a CONTIGUOUS run of 12 (W1) / 4 (W2) uint32:
//   W1: g_W1[((kt*2+wn)*3+g)*128 + lane*4 + j],  flatr=g*4+j,
//       nt = wn*6 + flatr/2, r = flatr&1,
//       k0 = kt*16 + (lane&3)*2 + r*8, n = nt*8 + lane/4 -> half2{W[k0,n],W[k0+1,n]}
//   W2: g_W2[(kt*2+wn)*128 + lane*4 + j], flatr=j, nt = wn*2 + j/2, r = j&1.
// ---------------------------------------------------------------------------
__global__ void prep_kernel(const float* __restrict__ wss_s, const float* __restrict__ wvv_s,
                            const float* __restrict__ wss_g, const float* __restrict__ wvv_g,
                            const float* __restrict__ wsv_v, const float* __restrict__ wvs_v) {
    int t = blockIdx.x * blockDim.x + threadIdx.x;
    const float A_SS = rsqrtf(8192.0f);
    const float A_VV = rsqrtf(6144.0f);
    const float A_SV = rsqrtf(12288.0f);

    if (t < 320 * 2 * 3 * 32) {
        int lane = t & 31;
        int g    = (t >> 5) % 3;
        int wn   = (t / 96) & 1;
        int kt   = t / 192;
#pragma unroll
        for (int j = 0; j < 4; ++j) {
            int flatr = g * 4 + j;
            int nt = wn * 6 + (flatr >> 1);
            int r  = flatr & 1;
            int n  = nt * 8 + (lane >> 2);
            float f[2];
#pragma unroll
            for (int q = 0; q < 2; ++q) {
                int k = kt * 16 + (lane & 3) * 2 + r * 8 + q;
                float val;
                if (k < 4096) {
                    int u = k >> 6, v = k & 63;
                    val = (n < 64) ? A_SS * wss_s[(u * 64 + v) * 64 + n]
                                   : A_SS * wss_g[(u * 64 + v) * 32 + (n - 64)];
                } else {
                    int kk = k - 4096, u = kk >> 5, v = kk & 31;
                    val = (n < 64) ? A_VV * wvv_s[(u * 32 + v) * 64 + n]
                                   : A_VV * wvv_g[(u * 32 + v) * 32 + (n - 64)];
                }
                f[q] = val;
            }
            __half2 h = __floats2half2_rn(f[0], f[1]);
            g_W1[((kt * 2 + wn) * 3 + g) * 128 + lane * 4 + j] = *(uint32_t*)&h;
        }
    } else if (t < 320 * 2 * 3 * 32 + 256 * 2 * 32) {
        int t2 = t - 320 * 2 * 3 * 32;
        int lane = t2 & 31;
        int wn   = (t2 >> 5) & 1;
        int kt   = t2 >> 6;
#pragma unroll
        for (int j = 0; j < 4; ++j) {
            int nt = wn * 2 + (j >> 1);
            int r  = j & 1;
            int n  = nt * 8 + (lane >> 2);
            float f[2];
#pragma unroll
            for (int q = 0; q < 2; ++q) {
                int k = kt * 16 + (lane & 3) * 2 + r * 8 + q;
                float val;
                if (k < 2048) { int u = k >> 5, v = k & 31; val = A_SV * wsv_v[(u * 32 + v) * 32 + n]; }
                else { int kk = k - 2048, u = kk >> 6, v = kk & 63; val = A_SV * wvs_v[(u * 64 + v) * 32 + n]; }
            f[q] = val;
            }
            __half2 h = __floats2half2_rn(f[0], f[1]);
            g_W2[(kt * 2 + wn) * 128 + lane * 4 + j] = *(uint32_t*)&h;
        }
    }
}

// ---------------------------------------------------------------------------
// Main fused kernel: 512 threads (16 warps), wm=warp&7 -> M-tile, wn=warp>>3
// -> N-half. Barrier-free mainloops with depth-2 B prefetch.
// ---------------------------------------------------------------------------
__global__ void __launch_bounds__(NTHR, 1)
main_kernel(const float* __restrict__ f1, const float* __restrict__ f2,
            const float* __restrict__ wl_s_g, const float* __restrict__ wl_v_g,
            float* __restrict__ out, int E) {
    extern __shared__ char sm[];
    __half* s1h = (__half*)(sm + OFF_S1);
    __half* s2h = (__half*)(sm + OFF_S2);
    __half* v1h = (__half*)(sm + OFF_V1);
    __half* v2h = (__half*)(sm + OFF_V2);
    float*  zsg = (float*)(sm + OFF_ZSG);
    float*  zv  = (float*)(sm + OFF_S1);
    float*  wls = (float*)(sm + OFF_V2);
    float*  wlv = (float*)(sm + OFF_V2 + 16384);

    const int tid  = threadIdx.x;
    const int warp = tid >> 5;
    const int lane = tid & 31;
    const int wm   = warp & 7;
    const int wn   = warp >> 3;
    const int e0   = blockIdx.x * TILE_E;

    // ---- stage inputs as fp16 (zero-padded past E) ----
    for (int idx = tid; idx < TILE_E * 160; idx += NTHR) {
        int e = idx / 160;
        int c = idx - e * 160;
        float a = 0.f, b = 0.f;
        if (e0 + e < E) {
            a = f1[(size_t)(e0 + e) * 160 + c];
            b = f2[(size_t)(e0 + e) * 160 + c];
        }
        if (c < 64) {
            s1h[e * P_S1 + c] = __float2half_rn(a);
            s2h[e * P_S2 + c] = __float2half_rn(b);
        } else {
            int cc = c - 64;
            int u = cc / 3, i = cc - u * 3;
            v1h[(i * 128 + e) * P_V1 + u] = __float2half_rn(a);
            v2h[(i * 128 + e) * P_V2 + u] = __float2half_rn(b);
        }
    }
    __syncthreads();

    const int r0 = wm * 16 + (lane >> 2);
    const __half* lm_s2 = s2h + (wm * 16 + (lane & 15)) * P_S2 + ((lane >> 4) << 3);
    const __half* lm_v2 = v2h + (wm * 16 + (lane & 15)) * P_V2 + ((lane >> 4) << 3);

    // ---- hoist ALL A-side fragments (reused across the entire K dim) ----
    uint32_t fs2[4][4];
    uint32_t fv2[3][2][4];
#pragma unroll
    for (int j = 0; j < 4; ++j) ldm4(fs2[j], lm_s2 + j * 16);
#pragma unroll
    for (int i = 0; i < 3; ++i)
#pragma unroll
        for (int j = 0; j < 2; ++j)
            ldm4(fv2[i][j], lm_v2 + i * (128 * P_V2) + j * 16);
    __syncthreads();   // v2h dead after this; epilogue weights overwrite it

    // ---- load epilogue weights into smem (overlaps GEMM1) ----
    for (int idx = tid; idx < 4096; idx += NTHR) wls[idx] = wl_s_g[idx];
    for (int idx = tid; idx < 1024; idx += NTHR) wlv[idx] = wl_v_g[idx];

    // =========================== GEMM1 (barrier-free) ===========================
    // per-kt stride in uint4: 2*3*128/4 = 192; this warp's base slot:
    const uint4* gB1 = (const uint4*)g_W1 + (size_t)wn * 96 + lane;
    float acc1[6][4];
#pragma unroll
    for (int nt = 0; nt < 6; ++nt)
        acc1[nt][0] = acc1[nt][1] = acc1[nt][2] = acc1[nt][3] = 0.f;

    uint32_t Bst[2][12];
    loadB12(Bst[0], gB1);
    loadB12(Bst[1], gB1 + 192);

    for (int c = 0; c < 80; ++c) {
        if (c < 64) {                       // ss: X = s1[e,u=c] * s2[e,v]
            uint32_t ha = h2u(s1h[r0 * P_S1 + c]);
            uint32_t hb = h2u(s1h[(r0 + 8) * P_S1 + c]);
#pragma unroll
            for (int kl = 0; kl < 4; ++kl) {
                int kt = c * 4 + kl;
                uint32_t* B = Bst[kt & 1];
                uint32_t a[4];
                a[0] = hmul2u(fs2[kl][0], ha); a[1] = hmul2u(fs2[kl][1], hb);
                a[2] = hmul2u(fs2[kl][2], ha); a[3] = hmul2u(fs2[kl][3], hb);
#pragma unroll
                for (int nt = 0; nt < 6; ++nt)
                    mma_f16(acc1[nt], a, B[2 * nt], B[2 * nt + 1]);
                int ktn = (kt + 2 < 320) ? kt + 2 : 319;
                loadB12(B, gB1 + (size_t)ktn * 192);
            }
        } else {                            // vv: X = sum_i v1[e,u,i]*v2[e,v,i]
            int c2 = c - 64;
#pragma unroll
            for (int h = 0; h < 2; ++h) {
                int u = 2 * c2 + h;
                uint32_t ha[3], hb[3];
#pragma unroll
                for (int i = 0; i < 3; ++i) {
                    ha[i] = h2u(v1h[(i * 128 + r0) * P_V1 + u]);
                    hb[i] = h2u(v1h[(i * 128 + r0 + 8) * P_V1 + u]);
                }
#pragma unroll
                for (int vb = 0; vb < 2; ++vb) {
                    int kt = c * 4 + h * 2 + vb;
                    uint32_t* B = Bst[kt & 1];
                    uint32_t a[4];
                    a[0] = hmul2u(fv2[0][vb][0], ha[0]);
                    a[1] = hmul2u(fv2[0][vb][1], hb[0]);
                    a[2] = hmul2u(fv2[0][vb][2], ha[0]);
                    a[3] = hmul2u(fv2[0][vb][3], hb[0]);
#pragma unroll
                    for (int i = 1; i < 3; ++i) {
                        a[0] = hfma2u(fv2[i][vb][0], ha[i], a[0]);
                        a[1] = hfma2u(fv2[i][vb][1], hb[i], a[1]);
                        a[2] = hfma2u(fv2[i][vb][2], ha[i], a[2]);
                        a[3] = hfma2u(fv2[i][vb][3], hb[i], a[3]);
                    }
#pragma unroll
                    for (int nt = 0; nt < 6; ++nt)
                        mma_f16(acc1[nt], a, B[2 * nt], B[2 * nt + 1]);
                    int ktn = (kt + 2 < 320) ? kt + 2 : 319;
                    loadB12(B, gB1 + (size_t)ktn * 192);
                }
            }
        }
    }

    // ---- write back z_sg (fresh region; no barrier needed) ----
    {
        int row = wm * 16 + (lane >> 2);
        int colb = (lane & 3) * 2;
#pragma unroll
        for (int nt = 0; nt < 6; ++nt) {
            int col = (wn * 6 + nt) * 8 + colb;
            *(float2*)&zsg[row * 98 + col]       = make_float2(acc1[nt][0], acc1[nt][1]);
            *(float2*)&zsg[(row + 8) * 98 + col] = make_float2(acc1[nt][2], acc1[nt][3]);
        }
    }

    // =========================== GEMM2 (barrier-free) ===========================
    // per-kt stride in uint4: 2*128/4 = 64
    const uint4* gB2 = (const uint4*)g_W2 + (size_t)wn * 32 + lane;
    float acc2[3][2][4];
#pragma unroll
    for (int i = 0; i < 3; ++i)
#pragma unroll
        for (int nt = 0; nt < 2; ++nt)
            acc2[i][nt][0] = acc2[i][nt][1] = acc2[i][nt][2] = acc2[i][nt][3] = 0.f;

    uint32_t Cst[2][4];
    loadB4(Cst[0], gB2);
    loadB4(Cst[1], gB2 + 64);

    for (int c = 0; c < 32; ++c) {
        if (c < 16) {                       // X = s1[e,u] * v2[e,v,i]
#pragma unroll
            for (int uu = 0; uu < 4; ++uu) {
                int u = 4 * c + uu;
                uint32_t ha = h2u(s1h[r0 * P_S1 + u]);
                uint32_t hb = h2u(s1h[(r0 + 8) * P_S1 + u]);
#pragma unroll
                for (int vb = 0; vb < 2; ++vb) {
                    int kt = c * 8 + uu * 2 + vb;
                    uint32_t* C = Cst[kt & 1];
                    uint32_t ai[3][4];
#pragma unroll
                    for (int i = 0; i < 3; ++i) {
                        ai[i][0] = hmul2u(fv2[i][vb][0], ha);
                        ai[i][1] = hmul2u(fv2[i][vb][1], hb);
                        ai[i][2] = hmul2u(fv2[i][vb][2], ha);
                        ai[i][3] = hmul2u(fv2[i][vb][3], hb);
                    }
#pragma unroll
                    for (int nt = 0; nt < 2; ++nt) {
#pragma unroll
                        for (int i = 0; i < 3; ++i)
                            mma_f16(acc2[i][nt], ai[i], C[2 * nt], C[2 * nt + 1]);
                    }
                    int ktn = (kt + 2 < 256) ? kt + 2 : 255;
                    loadB4(C, gB2 + (size_t)ktn * 64);
                }
            }
        } else {                            // X = v1[e,u,i] * s2[e,v]
            int c2 = c - 16;
#pragma unroll
            for (int h = 0; h < 2; ++h) {
                int u = 2 * c2 + h;
                uint32_t ha[3], hb[3];
#pragma unroll
                for (int i = 0; i < 3; ++i) {
                    ha[i] = h2u(v1h[(i * 128 + r0) * P_V1 + u]);
                    hb[i] = h2u(v1h[(i * 128 + r0 + 8) * P_V1 + u]);
                }
#pragma unroll
                for (int vb = 0; vb < 4; ++vb) {
                    int kt = c * 8 + h * 4 + vb;
                    uint32_t* C = Cst[kt & 1];
                    uint32_t ai[3][4];
#pragma unroll
                    for (int i = 0; i < 3; ++i) {
                        ai[i][0] = hmul2u(fs2[vb][0], ha[i]);
                        ai[i][1] = hmul2u(fs2[vb][1], hb[i]);
                        ai[i][2] = hmul2u(fs2[vb][2], ha[i]);
                        ai[i][3] = hmul2u(fs2[vb][3], hb[i]);
                    }
#pragma unroll
                    for (int nt = 0; nt < 2; ++nt) {
#pragma unroll
                        for (int i = 0; i < 3; ++i)
                            mma_f16(acc2[i][nt], ai[i], C[2 * nt], C[2 * nt + 1]);
                    }
                    int ktn = (kt + 2 < 256) ? kt + 2 : 255;
                    loadB4(C, gB2 + (size_t)ktn * 64);
                }
            }
        }
    }

    __syncthreads();   // all GEMM2 smem reads done; zsg complete

    // ---- write back z_v (aliases input region; inputs dead) ----
    {
        int rr = wm * 16 + (lane >> 2);
        int colb = (lane & 3) * 2;
#pragma unroll
        for (int i = 0; i < 3; ++i)
#pragma unroll
            for (int nt = 0; nt < 2; ++nt) {
                int row = i * 128 + rr;
                int col = (wn * 2 + nt) * 8 + colb;
                *(float2*)&zv[row * 34 + col]       = make_float2(acc2[i][nt][0], acc2[i][nt][1]);
                *(float2*)&zv[(row + 8) * 34 + col] = make_float2(acc2[i][nt][2], acc2[i][nt][3]);
            }
    }

    // ---- activations on z_sg ----
    for (int idx = tid; idx < 128 * 96; idx += NTHR) {
        int e = idx / 96;
        int cc = idx - e * 96;
        float v = zsg[e * 98 + cc];
        float sg = 1.f / (1.f + __expf(-v));
        zsg[e * 98 + cc] = (cc < 64) ? v * sg : sg;
    }
    __syncthreads();

    // ---- gate z_v by sigmoid(z_g) ----
    for (int idx = tid; idx < 384 * 32; idx += NTHR) {
        int row = idx >> 5, v = idx & 31;
        int e = row & 127;
        zv[row * 34 + v] *= zsg[e * 98 + 64 + v];
    }
    __syncthreads();

    // ---- s_out: silu(z_s) @ wl_s * 1/8 ----
    {
        int e = tid >> 2;
        int wbase = (tid & 3) * 16;
        bool valid = (e0 + e) < E;
#pragma unroll
        for (int wb = 0; wb < 16; wb += 8) {
            float accs[8];
#pragma unroll
            for (int j = 0; j < 8; ++j) accs[j] = 0.f;
            for (int u = 0; u < 64; ++u) {
                float zs = zsg[e * 98 + u];
                float4 w0 = *(const float4*)&wls[u * 64 + wbase + wb];
                float4 w1 = *(const float4*)&wls[u * 64 + wbase + wb + 4];
                accs[0] += zs * w0.x; accs[1] += zs * w0.y;
                accs[2] += zs * w0.z; accs[3] += zs * w0.w;
                accs[4] += zs * w1.x; accs[5] += zs * w1.y;
                accs[6] += zs * w1.z; accs[7] += zs * w1.w;
            }
            if (valid) {
                float4 o0 = make_float4(accs[0] * 0.125f, accs[1] * 0.125f,
                                        accs[2] * 0.125f, accs[3] * 0.125f);
                float4 o1 = make_float4(accs[4] * 0.125f, accs[5] * 0.125f,
                                        accs[6] * 0.125f, accs[7] * 0.125f);
                *(float4*)&out[(size_t)(e0 + e) * 160 + wbase + wb]     = o0;
                *(float4*)&out[(size_t)(e0 + e) * 160 + wbase + wb + 4] = o1;
            }
        }
    }

    // ---- v_out: (g * z_v) @ wl_v * 1/sqrt(32) ----
    const float R32 = 0.17677669529663687f;
    for (int r = tid; r < 384; r += NTHR) {
        int i = r >> 7;
        int e = r & 127;
        float acc[32];
#pragma unroll
        for (int w = 0; w < 32; ++w) acc[w] = 0.f;
        for (int v = 0; v < 32; ++v) {
            float zval = zv[r * 34 + v];
#pragma unroll
            for (int w4 = 0; w4 < 32; w4 += 4) {
                float4 wv = *(const float4*)&wlv[v * 32 + w4];
                acc[w4]     += zval * wv.x;
                acc[w4 + 1] += zval * wv.y;
                acc[w4 + 2] += zval * wv.z;
                acc[w4 + 3] += zval * wv.w;
            }
        }
        if (e0 + e < E) {
#pragma unroll
            for (int w = 0; w < 32; ++w)
                out[(size_t)(e0 + e) * 160 + 64 + w * 3 + i] = acc[w] * R32;
        }
    }
}

// ---------------------------------------------------------------------------
extern "C" void kernel_launch(void* const* d_in, const int* in_sizes, int n_in,
                              void* d_out, int out_size) {
    const float* f1    = (const float*)d_in[0];
    const float* f2    = (const float*)d_in[1];
    const float* wss_s = (const float*)d_in[4];
    const float* wvv_s = (const float*)d_in[5];
    const float* wss_g = (const float*)d_in[6];
    const float* wvv_g = (const float*)d_in[7];
    const float* wsv_v = (const float*)d_in[8];
    const float* wvs_v = (const float*)d_in[9];
    const float* wl_s  = (const float*)d_in[10];
    const float* wl_v  = (const float*)d_in[11];
    float* out = (float*)d_out;

    int E = in_sizes[0] / 160;

    prep_kernel<<<304, 256>>>(wss_s, wvv_s, wss_g, wvv_g, wsv_v, wvs_v);

    cudaFuncSetAttribute(main_kernel, cudaFuncAttributeMaxDynamicSharedMemorySize,
                         SMEM_BYTES);
    int ntiles = (E + TILE_E - 1) / TILE_E;
    main_kernel<<<ntiles, NTHR, SMEM_BYTES>>>(f1, f2, wl_s, wl_v, out, E);
}